// round 5
// baseline (speedup 1.0000x reference)
#include <cuda_runtime.h>

// MaxAssigner2D, two-phase:
//   Phase 1 (streaming): xc[p] = max over 32 channels of x[p*32 .. p*32+31]
//   Phase 2 (stencil):   out[b,h,w] = max over taps
//       {(0,0),(-1,0),(-2,0),(0,-1),(0,-2),(-1,-1),(-2,-2)} of xc[b,h+dh,w+dw]
//   (out-of-image taps contribute 0, matching the reference zero pad)

#define BATCH 16
#define HGT   512
#define WID   512
#define CH    32
#define NPIX  (BATCH * HGT * WID)   // 4,194,304

__device__ float g_xc[NPIX];        // 16 MB scratch (allocation-free)

// ---------------- Phase 1: channel-max, exact-residency grid-stride --------
// 8 lanes per pixel: one coalesced LDG.128 each (512B contiguous per warp),
// shfl-xor reduce. 592 blocks = 148 SMs x 4 CTAs (forced by launch_bounds)
// -> all CTAs resident for the whole kernel, no wave-quantization tail.
#define K1_NT      256
#define K1_BLOCKS  (148 * 4)                      // 592
#define K1_GROUPS  (K1_BLOCKS * K1_NT / 8)        // 18,944 pixel groups

__global__ void __launch_bounds__(K1_NT, 4)
chanmax_kernel(const float* __restrict__ x)
{
    const int tid = blockIdx.x * K1_NT + threadIdx.x;
    const int gid = tid >> 3;           // pixel-group id
    const int chq = tid & 7;            // which float4 of 32 channels

    #pragma unroll 4
    for (int p = gid; p < NPIX; p += K1_GROUPS) {
        const float4 d = __ldg((const float4*)(x + (size_t)p * CH) + chq);
        float v = fmaxf(fmaxf(d.x, d.y), fmaxf(d.z, d.w));
        v = fmaxf(v, __shfl_xor_sync(0xffffffffu, v, 1));
        v = fmaxf(v, __shfl_xor_sync(0xffffffffu, v, 2));
        v = fmaxf(v, __shfl_xor_sync(0xffffffffu, v, 4));
        if (chq == 0) g_xc[p] = v;
    }
}

// ---------------- Phase 2: 7-tap stencil, single wave, vectorized ----------
// 512 blocks x 256 threads, TH=16 full-width strips. Data starts at smem
// col 4 (16B aligned); cols 2..3 are the zero left-halo. All fill loads are
// independent LDG.128; drain does 4 output columns per thread with STG.128.
#define TH     16
#define HALO   2
#define TROWS  (TH + HALO)        // 18
#define DATA0  4                  // first data column in smem row
#define SW     520                // 4 pad + 512 data + 4 tail pad (16B-aligned rows)
#define K2_NT  256
#define NQUAD  (WID / 4)          // 128 float4 per row

__global__ void __launch_bounds__(K2_NT)
stencil_kernel(float* __restrict__ out)
{
    __shared__ float s[TROWS * SW];    // 37,440 B

    const int tid  = threadIdx.x;
    const int img  = blockIdx.x / (HGT / TH);
    const int tile = blockIdx.x % (HGT / TH);
    const int row0 = tile * TH;

    // zero the 2 left-halo columns (smem cols 2,3) for all 18 rows
    if (tid < TROWS * HALO) {
        int r = tid / HALO, c = tid % HALO;
        s[r * SW + HALO + c] = 0.0f;
    }

    // Fill: 18 rows x 128 float4, 9 independent LDG.128 + STS.128 per thread.
    {
        const int q  = tid & (NQUAD - 1);
        const int rr = tid >> 7;          // 0 or 1
        const float* xc_img = g_xc + (size_t)img * HGT * WID;
        #pragma unroll
        for (int r = rr; r < TROWS; r += 2) {
            const int g = row0 + r - HALO;
            float4 v = make_float4(0.f, 0.f, 0.f, 0.f);
            if (g >= 0)
                v = __ldg((const float4*)(xc_img + (size_t)g * WID) + q);
            *(float4*)(s + r * SW + DATA0 + 4 * q) = v;
        }
    }
    __syncthreads();

    // Drain: each thread computes 4 consecutive output columns for 8 rows.
    {
        const int q  = tid & (NQUAD - 1);
        const int rr = tid >> 7;          // 0 or 1
        const int cb = DATA0 + 4 * q;     // smem col of output col 4q
        float4* oimg = (float4*)(out + ((size_t)img * HGT + row0) * WID) + q;

        #pragma unroll
        for (int r = rr; r < TH; r += 2) {
            const float* p0 = s + r * SW + cb;        // image row (h-2)
            const float* p1 = p0 + SW;                // (h-1)
            const float* p2 = p1 + SW;                // (h)
            const float4 a2 = *(const float4*)p2;
            const float4 a1 = *(const float4*)p1;
            const float4 a0 = *(const float4*)p0;
            const float t2m1 = p2[-1], t2m2 = p2[-2]; // row h,   cols -1,-2
            const float t1m1 = p1[-1];                // row h-1, col  -1
            const float t0m2 = p0[-2];                // row h-2, col  -2

            float4 m;
            // j=0: taps (0,0)(0,-1)(0,-2) (-1,0)(-1,-1) (-2,0)(-2,-2)
            m.x = fmaxf(fmaxf(fmaxf(a2.x, t2m1), fmaxf(t2m2, a1.x)),
                        fmaxf(t1m1, fmaxf(a0.x, t0m2)));
            m.y = fmaxf(fmaxf(fmaxf(a2.y, a2.x), fmaxf(t2m1, a1.y)),
                        fmaxf(a1.x, fmaxf(a0.y, t0m2 /*col-1? no: (-2,-2)->col(1-2)=-1*/)));
            // careful: for j, (-2,-2) tap is column j-2 of row h-2.
            // j=1 -> p0[-1]; recompute properly below.
            m.y = fmaxf(fmaxf(fmaxf(a2.y, a2.x), fmaxf(t2m1, a1.y)),
                        fmaxf(a1.x, fmaxf(a0.y, p0[-1])));
            m.z = fmaxf(fmaxf(fmaxf(a2.z, a2.y), fmaxf(a2.x, a1.z)),
                        fmaxf(a1.y, fmaxf(a0.z, a0.x)));
            m.w = fmaxf(fmaxf(fmaxf(a2.w, a2.z), fmaxf(a2.y, a1.w)),
                        fmaxf(a1.z, fmaxf(a0.w, a0.y)));

            oimg[(size_t)r * NQUAD] = m;
        }
    }
}

extern "C" void kernel_launch(void* const* d_in, const int* in_sizes, int n_in,
                              void* d_out, int out_size)
{
    (void)in_sizes; (void)n_in; (void)out_size;
    const float* x = (const float*)d_in[0];
    float* out = (float*)d_out;

    chanmax_kernel<<<K1_BLOCKS, K1_NT>>>(x);
    stencil_kernel<<<BATCH * (HGT / TH), K2_NT>>>(out);
}

// round 6
// speedup vs baseline: 1.1130x; 1.1130x over previous
#include <cuda_runtime.h>

// MaxAssigner2D, two-phase:
//   Phase 1 (streaming): xc[p] = max over 32 channels of x[p*32 .. p*32+31]
//   Phase 2 (stencil):   out[b,h,w] = max over taps
//       {(0,0),(-1,0),(-2,0),(0,-1),(0,-2),(-1,-1),(-2,-2)} of xc[b,h+dh,w+dw]
//   (out-of-image taps contribute 0, matching the reference zero pad)

#define BATCH 16
#define HGT   512
#define WID   512
#define CH    32
#define NPIX  (BATCH * HGT * WID)   // 4,194,304

__device__ float g_xc[NPIX];        // 16 MB scratch (allocation-free)

// ---------------- Phase 1: channel-max, pure streaming (R2 proven) ---------
// 8 lanes per pixel: one coalesced LDG.128 each (512B contiguous per warp),
// shfl-xor reduce over the 8-lane group. Exact trip count, no predicates.
#define K1_NT      256
#define K1_BLOCKS  2048
#define K1_GROUPS  (K1_BLOCKS * K1_NT / 8)        // 65,536 pixel groups / sweep
#define K1_ITERS   (NPIX / K1_GROUPS)             // 64, exact

__global__ void __launch_bounds__(K1_NT)
chanmax_kernel(const float* __restrict__ x)
{
    const int tid = blockIdx.x * K1_NT + threadIdx.x;
    const int gid = tid >> 3;           // pixel-group id
    const int chq = tid & 7;            // which float4 of 32 channels

    #pragma unroll 8
    for (int it = 0; it < K1_ITERS; it++) {
        const int p = it * K1_GROUPS + gid;
        const float4 d = __ldg((const float4*)(x + (size_t)p * CH) + chq);
        float v = fmaxf(fmaxf(d.x, d.y), fmaxf(d.z, d.w));
        v = fmaxf(v, __shfl_xor_sync(0xffffffffu, v, 1));
        v = fmaxf(v, __shfl_xor_sync(0xffffffffu, v, 2));
        v = fmaxf(v, __shfl_xor_sync(0xffffffffu, v, 4));
        if (chq == 0) g_xc[p] = v;
    }
}

// ---------------- Phase 2: 7-tap stencil, single fully-resident wave -------
// TH=8 full-width strips, 256 threads, 20.8KB smem -> 8 CTAs/SM (warp-cap).
// Grid = 16*64 = 1024 blocks < 148*8 = 1184 resident slots: ONE wave, no tail.
#define TH     8
#define HALO   2
#define TROWS  (TH + HALO)        // 10
#define DATA0  4                  // first data column in smem row (16B aligned)
#define SW     520                // 4 pad + 512 data + 4 tail pad
#define K2_NT  256
#define NQUAD  (WID / 4)          // 128 float4 per row
#define FILLQ  (TROWS * NQUAD)    // 1280 quads = 5 * 256 (exact)

__global__ void __launch_bounds__(K2_NT)
stencil_kernel(float* __restrict__ out)
{
    __shared__ float s[TROWS * SW];    // 20,800 B

    const int tid  = threadIdx.x;
    const int img  = blockIdx.x / (HGT / TH);
    const int tile = blockIdx.x % (HGT / TH);
    const int row0 = tile * TH;

    // zero the 2 left-halo columns (smem cols DATA0-2, DATA0-1) for all rows
    if (tid < TROWS * HALO) {
        int r = tid / HALO, c = tid % HALO;
        s[r * SW + (DATA0 - HALO) + c] = 0.0f;
    }

    // Fill: 10 rows x 128 quads; 5 independent LDG.128 + STS.128 per thread.
    {
        const float* xc_img = g_xc + (size_t)img * HGT * WID;
        #pragma unroll
        for (int i = 0; i < FILLQ / K2_NT; i++) {
            const int qq = i * K2_NT + tid;
            const int r  = qq >> 7;            // quad row
            const int q  = qq & (NQUAD - 1);   // quad col
            const int g  = row0 + r - HALO;
            float4 v = make_float4(0.f, 0.f, 0.f, 0.f);
            if (g >= 0)
                v = __ldg((const float4*)(xc_img + (size_t)g * WID) + q);
            *(float4*)(s + r * SW + DATA0 + 4 * q) = v;
        }
    }
    __syncthreads();

    // Drain: 8 rows x 128 quads = 1024 outputs; 4 float4 outputs per thread.
    {
        float4* oimg = (float4*)(out + ((size_t)img * HGT + row0) * WID);
        #pragma unroll
        for (int i = 0; i < (TH * NQUAD) / K2_NT; i++) {
            const int qq = i * K2_NT + tid;
            const int r  = qq >> 7;
            const int q  = qq & (NQUAD - 1);
            const float* p0 = s + r * SW + DATA0 + 4 * q;  // image row (h-2)
            const float* p1 = p0 + SW;                     // (h-1)
            const float* p2 = p1 + SW;                     // (h)
            const float4 a2 = *(const float4*)p2;
            const float4 a1 = *(const float4*)p1;
            const float4 a0 = *(const float4*)p0;
            const float t2m1 = p2[-1], t2m2 = p2[-2];
            const float t1m1 = p1[-1];
            const float t0m2 = p0[-2], t0m1 = p0[-1];

            float4 m;
            // taps: (0,0)(0,-1)(0,-2) | (-1,0)(-1,-1) | (-2,0)(-2,-2)
            m.x = fmaxf(fmaxf(fmaxf(a2.x, t2m1), fmaxf(t2m2, a1.x)),
                        fmaxf(t1m1, fmaxf(a0.x, t0m2)));
            m.y = fmaxf(fmaxf(fmaxf(a2.y, a2.x), fmaxf(t2m1, a1.y)),
                        fmaxf(a1.x, fmaxf(a0.y, t0m1)));
            m.z = fmaxf(fmaxf(fmaxf(a2.z, a2.y), fmaxf(a2.x, a1.z)),
                        fmaxf(a1.y, fmaxf(a0.z, a0.x)));
            m.w = fmaxf(fmaxf(fmaxf(a2.w, a2.z), fmaxf(a2.y, a1.w)),
                        fmaxf(a1.z, fmaxf(a0.w, a0.y)));

            oimg[(size_t)r * NQUAD + q] = m;
        }
    }
}

extern "C" void kernel_launch(void* const* d_in, const int* in_sizes, int n_in,
                              void* d_out, int out_size)
{
    (void)in_sizes; (void)n_in; (void)out_size;
    const float* x = (const float*)d_in[0];
    float* out = (float*)d_out;

    chanmax_kernel<<<K1_BLOCKS, K1_NT>>>(x);
    stencil_kernel<<<BATCH * (HGT / TH), K2_NT>>>(out);
}

// round 7
// speedup vs baseline: 1.1291x; 1.0145x over previous
#include <cuda_runtime.h>

// MaxAssigner2D, two-phase:
//   Phase 1 (streaming): xc[p] = max over 32 channels of x[p*32 .. p*32+31]
//   Phase 2 (stencil):   out[b,h,w] = max over taps
//       {(0,0),(-1,0),(-2,0),(0,-1),(0,-2),(-1,-1),(-2,-2)} of xc[b,h+dh,w+dw]
//   (out-of-image taps contribute 0, matching the reference zero pad)

#define BATCH 16
#define HGT   512
#define WID   512
#define CH    32
#define NPIX  (BATCH * HGT * WID)   // 4,194,304

__device__ float g_xc[NPIX];        // 16 MB scratch (allocation-free)

// ---------------- Phase 1: channel-max, pure streaming (R2 proven) ---------
// 8 lanes per pixel: one coalesced LDG.128 each (512B contiguous per warp),
// shfl-xor reduce over the 8-lane group. Exact trip count, no predicates.
#define K1_NT      256
#define K1_BLOCKS  2048
#define K1_GROUPS  (K1_BLOCKS * K1_NT / 8)        // 65,536 pixel groups / sweep
#define K1_ITERS   (NPIX / K1_GROUPS)             // 64, exact

__global__ void __launch_bounds__(K1_NT)
chanmax_kernel(const float* __restrict__ x)
{
    const int tid = blockIdx.x * K1_NT + threadIdx.x;
    const int gid = tid >> 3;           // pixel-group id
    const int chq = tid & 7;            // which float4 of 32 channels

    #pragma unroll 8
    for (int it = 0; it < K1_ITERS; it++) {
        const int p = it * K1_GROUPS + gid;
        const float4 d = __ldg((const float4*)(x + (size_t)p * CH) + chq);
        float v = fmaxf(fmaxf(d.x, d.y), fmaxf(d.z, d.w));
        v = fmaxf(v, __shfl_xor_sync(0xffffffffu, v, 1));
        v = fmaxf(v, __shfl_xor_sync(0xffffffffu, v, 2));
        v = fmaxf(v, __shfl_xor_sync(0xffffffffu, v, 4));
        if (chq == 0) g_xc[p] = v;
    }
}

// ---------------- Phase 2: direct-load 7-tap stencil (no smem, no barrier) -
// One output float4 per thread from 6 independent loads (L2-hot xc).
// All loads front-batched -> MLP=6/thread, no shuffles, no sync.
#define K2_NT     256
#define K2_BLOCKS (NPIX / 4 / K2_NT)    // 4096

__global__ void __launch_bounds__(K2_NT)
stencil_kernel(const float* __restrict__ xc, float* __restrict__ out)
{
    const int p   = blockIdx.x * K2_NT + threadIdx.x;  // quad id
    const int q   = p & 127;            // quad within row (cols 4q..4q+3)
    const int h   = (p >> 7) & 511;     // image row
    // img = p >> 16 folded into flat addressing below.

    const float* base = xc + ((size_t)p << 2);   // &xc[img][h][4q]

    // Row h: always valid.
    const float4 a2 = __ldg((const float4*)base);
    float2 l2 = make_float2(0.f, 0.f);           // cols 4q-2, 4q-1 of row h
    if (q) l2 = __ldg((const float2*)(base - 2));

    // Rows h-1, h-2: may be above the image (zero pad).
    float4 a1 = make_float4(0.f, 0.f, 0.f, 0.f);
    float4 a0 = make_float4(0.f, 0.f, 0.f, 0.f);
    float  l1 = 0.f;                             // col 4q-1 of row h-1
    float2 l0 = make_float2(0.f, 0.f);           // cols 4q-2, 4q-1 of row h-2
    if (h >= 1) {
        a1 = __ldg((const float4*)(base - WID));
        if (q) l1 = __ldg(base - WID - 1);
    }
    if (h >= 2) {
        a0 = __ldg((const float4*)(base - 2 * WID));
        if (q) l0 = __ldg((const float2*)(base - 2 * WID - 2));
    }

    // taps per output col j: (0,j)(0,j-1)(0,j-2) | (-1,j)(-1,j-1) | (-2,j)(-2,j-2)
    float4 m;
    m.x = fmaxf(fmaxf(fmaxf(a2.x, l2.y), fmaxf(l2.x, a1.x)),
                fmaxf(l1,   fmaxf(a0.x, l0.x)));
    m.y = fmaxf(fmaxf(fmaxf(a2.y, a2.x), fmaxf(l2.y, a1.y)),
                fmaxf(a1.x, fmaxf(a0.y, l0.y)));
    m.z = fmaxf(fmaxf(fmaxf(a2.z, a2.y), fmaxf(a2.x, a1.z)),
                fmaxf(a1.y, fmaxf(a0.z, a0.x)));
    m.w = fmaxf(fmaxf(fmaxf(a2.w, a2.z), fmaxf(a2.y, a1.w)),
                fmaxf(a1.z, fmaxf(a0.w, a0.y)));

    ((float4*)out)[p] = m;
}

extern "C" void kernel_launch(void* const* d_in, const int* in_sizes, int n_in,
                              void* d_out, int out_size)
{
    (void)in_sizes; (void)n_in; (void)out_size;
    const float* x = (const float*)d_in[0];
    float* out = (float*)d_out;

    float* xc_ptr;
    cudaGetSymbolAddress((void**)&xc_ptr, g_xc);

    chanmax_kernel<<<K1_BLOCKS, K1_NT>>>(x);
    stencil_kernel<<<K2_BLOCKS, K2_NT>>>(xc_ptr, out);
}

// round 8
// speedup vs baseline: 1.1389x; 1.0087x over previous
#include <cuda_runtime.h>

// MaxAssigner2D, two-phase:
//   Phase 1 (streaming): xc[p] = max over 32 channels of x[p*32 .. p*32+31]
//   Phase 2 (stencil):   out[b,h,w] = max over taps
//       {(0,0),(-1,0),(-2,0),(0,-1),(0,-2),(-1,-1),(-2,-2)} of xc[b,h+dh,w+dw]
//   (out-of-image taps contribute 0, matching the reference zero pad)

#define BATCH 16
#define HGT   512
#define WID   512
#define CH    32
#define NPIX  (BATCH * HGT * WID)   // 4,194,304
#define NQUAD (WID / 4)             // 128

__device__ float g_xc[NPIX];        // 16 MB scratch (allocation-free)

// ---------------- Phase 1: channel-max, pure streaming (R2 proven) ---------
#define K1_NT      256
#define K1_BLOCKS  2048
#define K1_GROUPS  (K1_BLOCKS * K1_NT / 8)        // 65,536 pixel groups / sweep
#define K1_ITERS   (NPIX / K1_GROUPS)             // 64, exact

__global__ void __launch_bounds__(K1_NT)
chanmax_kernel(const float* __restrict__ x)
{
    const int tid = blockIdx.x * K1_NT + threadIdx.x;
    const int gid = tid >> 3;           // pixel-group id
    const int chq = tid & 7;            // which float4 of 32 channels

    #pragma unroll 8
    for (int it = 0; it < K1_ITERS; it++) {
        const int p = it * K1_GROUPS + gid;
        const float4 d = __ldg((const float4*)(x + (size_t)p * CH) + chq);
        float v = fmaxf(fmaxf(d.x, d.y), fmaxf(d.z, d.w));
        v = fmaxf(v, __shfl_xor_sync(0xffffffffu, v, 1));
        v = fmaxf(v, __shfl_xor_sync(0xffffffffu, v, 2));
        v = fmaxf(v, __shfl_xor_sync(0xffffffffu, v, 4));
        if (chq == 0) g_xc[p] = v;
    }
}

// ---------------- Phase 2: direct-load stencil, 4col x 2row per thread -----
// Row factorization: out(h) = max(M0(h), M1(h-1), M2(h-2)) with
//   M0 = max(a, a<<1, a<<2), M1 = max(a, a<<1), M2 = max(a, a<<2).
// 8 independent loads (4 rows x [float4 + float2]) -> 8 outputs.
#define K2_NT     256
#define K2_BLOCKS (NPIX / 8 / K2_NT)    // 2048

__global__ void __launch_bounds__(K2_NT)
stencil_kernel(const float* __restrict__ xc, float* __restrict__ out)
{
    const int p   = blockIdx.x * K2_NT + threadIdx.x;  // patch id
    const int q   = p & (NQUAD - 1);      // quad col (cols 4q..4q+3)
    const int hg  = (p >> 7) & 255;       // row-pair within image
    const int h0  = hg * 2;               // even
    const int img = p >> 15;

    const float* base = xc + ((size_t)img * HGT + h0) * WID + 4 * q;

    const float4 z4 = make_float4(0.f, 0.f, 0.f, 0.f);
    const float2 z2 = make_float2(0.f, 0.f);

    // Front-batched independent loads (predicated, never branch-divergent in h)
    const float4 A0 = __ldg((const float4*)base);                 // row h0
    const float4 A1 = __ldg((const float4*)(base + WID));         // row h0+1
    const float2 L0 = q ? __ldg((const float2*)(base - 2))       : z2;
    const float2 L1 = q ? __ldg((const float2*)(base + WID - 2)) : z2;
    const bool up = (h0 >= 2);            // h0 even: h0>=2 covers both halo rows
    const float4 Am1 = up ? __ldg((const float4*)(base - WID))     : z4;
    const float4 Am2 = up ? __ldg((const float4*)(base - 2 * WID)) : z4;
    const float2 Lm1 = (up && q) ? __ldg((const float2*)(base - WID - 2))     : z2;
    const float2 Lm2 = (up && q) ? __ldg((const float2*)(base - 2 * WID - 2)) : z2;

    // Per-row horizontal maxes. e[-2]=L.x, e[-1]=L.y, e[0..3]=A.
    // M1 (shift 0,1) for rows h0-1, h0, h0+1; M0 (0,1,2) for h0, h0+1;
    // M2 (0,2) for rows h0-2, h0-1.
    float4 M1_0, M1_1, M1_m1, M0_0, M0_1, M2_m1, M2_m2;

    M1_0.x = fmaxf(A0.x, L0.y);  M1_0.y = fmaxf(A0.y, A0.x);
    M1_0.z = fmaxf(A0.z, A0.y);  M1_0.w = fmaxf(A0.w, A0.z);
    M0_0.x = fmaxf(M1_0.x, L0.x); M0_0.y = fmaxf(M1_0.y, L0.y);
    M0_0.z = fmaxf(M1_0.z, A0.x); M0_0.w = fmaxf(M1_0.w, A0.y);

    M1_1.x = fmaxf(A1.x, L1.y);  M1_1.y = fmaxf(A1.y, A1.x);
    M1_1.z = fmaxf(A1.z, A1.y);  M1_1.w = fmaxf(A1.w, A1.z);
    M0_1.x = fmaxf(M1_1.x, L1.x); M0_1.y = fmaxf(M1_1.y, L1.y);
    M0_1.z = fmaxf(M1_1.z, A1.x); M0_1.w = fmaxf(M1_1.w, A1.y);

    M1_m1.x = fmaxf(Am1.x, Lm1.y); M1_m1.y = fmaxf(Am1.y, Am1.x);
    M1_m1.z = fmaxf(Am1.z, Am1.y); M1_m1.w = fmaxf(Am1.w, Am1.z);

    M2_m1.x = fmaxf(Am1.x, Lm1.x); M2_m1.y = fmaxf(Am1.y, Lm1.y);
    M2_m1.z = fmaxf(Am1.z, Am1.x); M2_m1.w = fmaxf(Am1.w, Am1.y);

    M2_m2.x = fmaxf(Am2.x, Lm2.x); M2_m2.y = fmaxf(Am2.y, Lm2.y);
    M2_m2.z = fmaxf(Am2.z, Am2.x); M2_m2.w = fmaxf(Am2.w, Am2.y);

    float4 o0, o1;   // out rows h0, h0+1
    o0.x = fmaxf(M0_0.x, fmaxf(M1_m1.x, M2_m2.x));
    o0.y = fmaxf(M0_0.y, fmaxf(M1_m1.y, M2_m2.y));
    o0.z = fmaxf(M0_0.z, fmaxf(M1_m1.z, M2_m2.z));
    o0.w = fmaxf(M0_0.w, fmaxf(M1_m1.w, M2_m2.w));

    o1.x = fmaxf(M0_1.x, fmaxf(M1_0.x, M2_m1.x));
    o1.y = fmaxf(M0_1.y, fmaxf(M1_0.y, M2_m1.y));
    o1.z = fmaxf(M0_1.z, fmaxf(M1_0.z, M2_m1.z));
    o1.w = fmaxf(M0_1.w, fmaxf(M1_0.w, M2_m1.w));

    float4* oq = (float4*)out + ((size_t)img * HGT + h0) * NQUAD + q;
    oq[0]     = o0;
    oq[NQUAD] = o1;
}

extern "C" void kernel_launch(void* const* d_in, const int* in_sizes, int n_in,
                              void* d_out, int out_size)
{
    (void)in_sizes; (void)n_in; (void)out_size;
    const float* x = (const float*)d_in[0];
    float* out = (float*)d_out;

    float* xc_ptr;
    cudaGetSymbolAddress((void**)&xc_ptr, g_xc);

    chanmax_kernel<<<K1_BLOCKS, K1_NT>>>(x);
    stencil_kernel<<<K2_BLOCKS, K2_NT>>>(xc_ptr, out);
}